// round 2
// baseline (speedup 1.0000x reference)
#include <cuda_runtime.h>
#include <math.h>

#define BB 8192
#define DD 256
#define NN 2048
#define KK 512
#define TT 8
#define EPSV 1e-10f

// ---- scratch (no allocations allowed) ----
__device__ float g_c[BB];       // 1 + td[b] - ||vhat_b||^2
__device__ float g_td[BB];      // ||vhat_b - v_b||^2
__device__ float g_maskf[BB];
__device__ float g_nn[NN];      // ||neg_n||^2
__device__ double g_acc[3];     // [0]=Ju numerator sum, [1]=Jt numerator sum, [2]=ortho sq sum

__global__ void zero_acc_kernel() {
    if (threadIdx.x < 3) g_acc[threadIdx.x] = 0.0;
}

// per-row stats for vhat / v / mask  (warp per row)
__global__ void prep_b_kernel(const float* __restrict__ v,
                              const float* __restrict__ vhat,
                              const unsigned char* __restrict__ mask) {
    int row = blockIdx.x * 8 + (threadIdx.x >> 5);
    int lane = threadIdx.x & 31;
    const float* vh = vhat + (size_t)row * DD;
    const float* vv = v + (size_t)row * DD;
    float td = 0.f, vn = 0.f;
#pragma unroll
    for (int i = 0; i < 8; i++) {
        float a = vh[lane + i * 32];
        float b = vv[lane + i * 32];
        float d = a - b;
        td += d * d;
        vn += a * a;
    }
#pragma unroll
    for (int o = 16; o; o >>= 1) {
        td += __shfl_xor_sync(0xFFFFFFFFu, td, o);
        vn += __shfl_xor_sync(0xFFFFFFFFu, vn, o);
    }
    if (lane == 0) {
        g_td[row] = td;
        g_maskf[row] = mask[row] ? 1.0f : 0.0f;
        g_c[row] = 1.0f + td - vn;
    }
}

// ||neg_n||^2  (warp per row)
__global__ void prep_n_kernel(const float* __restrict__ negs) {
    int row = blockIdx.x * 8 + (threadIdx.x >> 5);
    int lane = threadIdx.x & 31;
    const float* nr = negs + (size_t)row * DD;
    float nn = 0.f;
#pragma unroll
    for (int i = 0; i < 8; i++) {
        float a = nr[lane + i * 32];
        nn += a * a;
    }
#pragma unroll
    for (int o = 16; o; o >>= 1) nn += __shfl_xor_sync(0xFFFFFFFFu, nn, o);
    if (lane == 0) g_nn[row] = nn;
}

// 128x128 tiled A*B^T with fused reduction epilogue.
// MODE 0: Ju hinge  sum_{m,n} maskf[m]*max(c[m]-nn[n]+2*dot, 0)   -> g_acc[0]
// MODE 1: ortho     sum_{m,n} (dot - (m==n))^2                    -> g_acc[2]
template <int MODE>
__global__ __launch_bounds__(256)
void gemm_reduce_kernel(const float* __restrict__ A,
                        const float* __restrict__ Bm,
                        int Kdim) {
    __shared__ float As[8][128];
    __shared__ float Bs[8][128];

    int tid = threadIdx.x;
    int tx = tid & 15;        // 0..15 (n direction)
    int ty = tid >> 4;        // 0..15 (m direction)
    int m0 = blockIdx.y * 128;
    int n0 = blockIdx.x * 128;

    int lrow = tid >> 1;            // 0..127
    int lcol = (tid & 1) * 4;       // 0 or 4

    const float* Aptr = A + (size_t)(m0 + lrow) * Kdim + lcol;
    const float* Bptr = Bm + (size_t)(n0 + lrow) * Kdim + lcol;

    float acc[8][8];
#pragma unroll
    for (int i = 0; i < 8; i++)
#pragma unroll
        for (int j = 0; j < 8; j++) acc[i][j] = 0.f;

    for (int k0 = 0; k0 < Kdim; k0 += 8) {
        float4 av = *(const float4*)(Aptr + k0);
        float4 bv = *(const float4*)(Bptr + k0);
        __syncthreads();
        As[lcol + 0][lrow] = av.x;
        As[lcol + 1][lrow] = av.y;
        As[lcol + 2][lrow] = av.z;
        As[lcol + 3][lrow] = av.w;
        Bs[lcol + 0][lrow] = bv.x;
        Bs[lcol + 1][lrow] = bv.y;
        Bs[lcol + 2][lrow] = bv.z;
        Bs[lcol + 3][lrow] = bv.w;
        __syncthreads();
#pragma unroll
        for (int k = 0; k < 8; k++) {
            float a[8], b[8];
            *(float4*)(a)     = *(const float4*)&As[k][ty * 8];
            *(float4*)(a + 4) = *(const float4*)&As[k][ty * 8 + 4];
            *(float4*)(b)     = *(const float4*)&Bs[k][tx * 8];
            *(float4*)(b + 4) = *(const float4*)&Bs[k][tx * 8 + 4];
#pragma unroll
            for (int i = 0; i < 8; i++)
#pragma unroll
                for (int j = 0; j < 8; j++) acc[i][j] = fmaf(a[i], b[j], acc[i][j]);
        }
    }

    // ---- epilogue ----
    float sum = 0.f;
    if (MODE == 0) {
        float nnv[8];
#pragma unroll
        for (int j = 0; j < 8; j++) nnv[j] = g_nn[n0 + tx * 8 + j];
#pragma unroll
        for (int i = 0; i < 8; i++) {
            int m = m0 + ty * 8 + i;
            float ci = g_c[m];
            float mf = g_maskf[m];
            float s = 0.f;
#pragma unroll
            for (int j = 0; j < 8; j++) {
                float p = ci - nnv[j] + 2.0f * acc[i][j];
                s += fmaxf(p, 0.f);
            }
            sum += mf * s;
        }
    } else {
#pragma unroll
        for (int i = 0; i < 8; i++) {
            int m = m0 + ty * 8 + i;
#pragma unroll
            for (int j = 0; j < 8; j++) {
                int n = n0 + tx * 8 + j;
                float gv = acc[i][j] - (m == n ? 1.0f : 0.0f);
                sum += gv * gv;
            }
        }
    }

    // block reduce
#pragma unroll
    for (int o = 16; o; o >>= 1) sum += __shfl_xor_sync(0xFFFFFFFFu, sum, o);
    __syncthreads();
    float* red = &As[0][0];
    if ((tid & 31) == 0) red[tid >> 5] = sum;
    __syncthreads();
    if (tid == 0) {
        float tot = 0.f;
#pragma unroll
        for (int w = 0; w < 8; w++) tot += red[w];
        atomicAdd(&g_acc[MODE == 0 ? 0 : 2], (double)tot);
    }
}

// focal triplet term: warp per row
__global__ void jt_kernel(const float* __restrict__ g,
                          const float* __restrict__ F,
                          const float* __restrict__ vhat) {
    int row = blockIdx.x * 8 + (threadIdx.x >> 5);
    int lane = threadIdx.x & 31;

    float gl[16];
#pragma unroll
    for (int i = 0; i < 16; i++) gl[i] = g[(size_t)row * KK + i * 32 + lane];

    float vh[8];
#pragma unroll
    for (int i = 0; i < 8; i++) vh[i] = vhat[(size_t)row * DD + lane * 8 + i];

    float cv[TT];
    int ci[TT];
#pragma unroll
    for (int t = 0; t < TT; t++) {
        // local min over 16 (lowest local index wins ties -> lowest global idx per lane)
        float mv = gl[0];
        int mi = 0;
#pragma unroll
        for (int i = 1; i < 16; i++) {
            if (gl[i] < mv) { mv = gl[i]; mi = i; }
        }
        float bv = mv;
        int bidx = mi * 32 + lane;
#pragma unroll
        for (int o = 16; o; o >>= 1) {
            float ov = __shfl_xor_sync(0xFFFFFFFFu, bv, o);
            int oi = __shfl_xor_sync(0xFFFFFFFFu, bidx, o);
            if (ov < bv || (ov == bv && oi < bidx)) { bv = ov; bidx = oi; }
        }
        cv[t] = bv;
        ci[t] = bidx;
        if ((bidx & 31) == lane) gl[bidx >> 5] = 3.4e38f;  // exclude
    }

    float gsum = 0.f;
#pragma unroll
    for (int t = 0; t < TT; t++) gsum += cv[t];
    float denom = gsum + EPSV;
    float td = g_td[row];

    float jt = 0.f;
#pragma unroll
    for (int t = 0; t < TT; t++) {
        const float* Fr = F + (size_t)ci[t] * DD + lane * 8;
        float a = 0.f;
        float4 f0 = *(const float4*)(Fr);
        float4 f1 = *(const float4*)(Fr + 4);
        float d0 = vh[0] - f0.x; a += d0 * d0;
        float d1 = vh[1] - f0.y; a += d1 * d1;
        float d2 = vh[2] - f0.z; a += d2 * d2;
        float d3 = vh[3] - f0.w; a += d3 * d3;
        float d4 = vh[4] - f1.x; a += d4 * d4;
        float d5 = vh[5] - f1.y; a += d5 * d5;
        float d6 = vh[6] - f1.z; a += d6 * d6;
        float d7 = vh[7] - f1.w; a += d7 * d7;
#pragma unroll
        for (int o = 16; o; o >>= 1) a += __shfl_xor_sync(0xFFFFFFFFu, a, o);
        float gt = cv[t] / denom;
        float om = 1.0f - gt;
        float mt = om * om;                 // M_MARGIN = 1.0
        jt += fmaxf(mt + td - a, 0.f);
    }
    if (lane == 0) atomicAdd(&g_acc[1], (double)(jt * g_maskf[row]));
}

__global__ void finalize_kernel(const unsigned char* __restrict__ mask,
                                float* __restrict__ out) {
    __shared__ float sm[256];
    float s = 0.f;
    for (int i = threadIdx.x; i < BB; i += 256) s += mask[i] ? 1.0f : 0.0f;
    sm[threadIdx.x] = s;
    __syncthreads();
    for (int o = 128; o; o >>= 1) {
        if (threadIdx.x < o) sm[threadIdx.x] += sm[threadIdx.x + o];
        __syncthreads();
    }
    if (threadIdx.x == 0) {
        double msum = (double)sm[0];
        double ju = (msum == 0.0) ? 0.0 : g_acc[0] / ((double)NN * msum);
        double jt = (msum == 0.0) ? 0.0 : g_acc[1] / msum;
        double jz = ju + jt + 1e-3 * g_acc[2];   // lambda * ortho^2 == lambda * sum(gram^2)
        out[0] = (float)jz;
    }
}

extern "C" void kernel_launch(void* const* d_in, const int* in_sizes, int n_in,
                              void* d_out, int out_size) {
    const float* v = (const float*)d_in[0];
    const float* vhat = (const float*)d_in[1];
    const float* g = (const float*)d_in[2];
    const float* F = (const float*)d_in[3];
    const float* negs = (const float*)d_in[4];
    const unsigned char* mask = (const unsigned char*)d_in[5];
    float* out = (float*)d_out;

    zero_acc_kernel<<<1, 32>>>();
    prep_b_kernel<<<BB / 8, 256>>>(v, vhat, mask);
    prep_n_kernel<<<NN / 8, 256>>>(negs);

    // Ju: A = vhat [8192 x 256], B = negatives [2048 x 256]
    dim3 gJu(NN / 128, BB / 128);
    gemm_reduce_kernel<0><<<gJu, 256>>>(vhat, negs, DD);

    // ortho: F @ F^T, 512x512
    dim3 gOr(KK / 128, KK / 128);
    gemm_reduce_kernel<1><<<gOr, 256>>>(F, F, DD);

    jt_kernel<<<BB / 8, 256>>>(g, F, vhat);

    finalize_kernel<<<1, 256>>>(mask, out);
}

// round 3
// speedup vs baseline: 1.0075x; 1.0075x over previous
#include <cuda_runtime.h>
#include <math.h>

#define BB 8192
#define DD 256
#define NN 2048
#define KK 512
#define TT 8
#define EPSV 1e-10f

// ---- scratch (no allocations allowed) ----
__device__ float g_c[BB];       // 1 + td[b] - ||vhat_b||^2
__device__ float g_td[BB];      // ||vhat_b - v_b||^2
__device__ float g_maskf[BB];
__device__ float g_nn[NN];      // ||neg_n||^2
__device__ double g_acc[3];     // [0]=Ju numerator sum, [1]=Jt numerator sum, [2]=ortho sq sum

__global__ void zero_acc_kernel() {
    if (threadIdx.x < 3) g_acc[threadIdx.x] = 0.0;
}

// per-row stats for vhat / v / mask  (warp per row)
__global__ void prep_b_kernel(const float* __restrict__ v,
                              const float* __restrict__ vhat,
                              const unsigned char* __restrict__ mask) {
    int row = blockIdx.x * 8 + (threadIdx.x >> 5);
    int lane = threadIdx.x & 31;
    const float* vh = vhat + (size_t)row * DD;
    const float* vv = v + (size_t)row * DD;
    float td = 0.f, vn = 0.f;
#pragma unroll
    for (int i = 0; i < 8; i++) {
        float a = vh[lane + i * 32];
        float b = vv[lane + i * 32];
        float d = a - b;
        td += d * d;
        vn += a * a;
    }
#pragma unroll
    for (int o = 16; o; o >>= 1) {
        td += __shfl_xor_sync(0xFFFFFFFFu, td, o);
        vn += __shfl_xor_sync(0xFFFFFFFFu, vn, o);
    }
    if (lane == 0) {
        g_td[row] = td;
        g_maskf[row] = mask[row] ? 1.0f : 0.0f;
        g_c[row] = 1.0f + td - vn;
    }
}

// ||neg_n||^2  (warp per row)
__global__ void prep_n_kernel(const float* __restrict__ negs) {
    int row = blockIdx.x * 8 + (threadIdx.x >> 5);
    int lane = threadIdx.x & 31;
    const float* nr = negs + (size_t)row * DD;
    float nn = 0.f;
#pragma unroll
    for (int i = 0; i < 8; i++) {
        float a = nr[lane + i * 32];
        nn += a * a;
    }
#pragma unroll
    for (int o = 16; o; o >>= 1) nn += __shfl_xor_sync(0xFFFFFFFFu, nn, o);
    if (lane == 0) g_nn[row] = nn;
}

// 128x128 tiled A*B^T with fused reduction epilogue.
// MODE 0: Ju hinge  sum_{m,n} maskf[m]*max(c[m]-nn[n]+2*dot, 0)   -> g_acc[0]
// MODE 1: ortho     sum_{m,n} (dot - (m==n))^2                    -> g_acc[2]
template <int MODE>
__global__ __launch_bounds__(256)
void gemm_reduce_kernel(const float* __restrict__ A,
                        const float* __restrict__ Bm,
                        int Kdim) {
    __shared__ float As[8][128];
    __shared__ float Bs[8][128];

    int tid = threadIdx.x;
    int tx = tid & 15;        // 0..15 (n direction)
    int ty = tid >> 4;        // 0..15 (m direction)
    int m0 = blockIdx.y * 128;
    int n0 = blockIdx.x * 128;

    int lrow = tid >> 1;            // 0..127
    int lcol = (tid & 1) * 4;       // 0 or 4

    const float* Aptr = A + (size_t)(m0 + lrow) * Kdim + lcol;
    const float* Bptr = Bm + (size_t)(n0 + lrow) * Kdim + lcol;

    float acc[8][8];
#pragma unroll
    for (int i = 0; i < 8; i++)
#pragma unroll
        for (int j = 0; j < 8; j++) acc[i][j] = 0.f;

    for (int k0 = 0; k0 < Kdim; k0 += 8) {
        float4 av = *(const float4*)(Aptr + k0);
        float4 bv = *(const float4*)(Bptr + k0);
        __syncthreads();
        As[lcol + 0][lrow] = av.x;
        As[lcol + 1][lrow] = av.y;
        As[lcol + 2][lrow] = av.z;
        As[lcol + 3][lrow] = av.w;
        Bs[lcol + 0][lrow] = bv.x;
        Bs[lcol + 1][lrow] = bv.y;
        Bs[lcol + 2][lrow] = bv.z;
        Bs[lcol + 3][lrow] = bv.w;
        __syncthreads();
#pragma unroll
        for (int k = 0; k < 8; k++) {
            float a[8], b[8];
            *(float4*)(a)     = *(const float4*)&As[k][ty * 8];
            *(float4*)(a + 4) = *(const float4*)&As[k][ty * 8 + 4];
            *(float4*)(b)     = *(const float4*)&Bs[k][tx * 8];
            *(float4*)(b + 4) = *(const float4*)&Bs[k][tx * 8 + 4];
#pragma unroll
            for (int i = 0; i < 8; i++)
#pragma unroll
                for (int j = 0; j < 8; j++) acc[i][j] = fmaf(a[i], b[j], acc[i][j]);
        }
    }

    // ---- epilogue ----
    float sum = 0.f;
    if (MODE == 0) {
        float nnv[8];
#pragma unroll
        for (int j = 0; j < 8; j++) nnv[j] = g_nn[n0 + tx * 8 + j];
#pragma unroll
        for (int i = 0; i < 8; i++) {
            int m = m0 + ty * 8 + i;
            float ci = g_c[m];
            float mf = g_maskf[m];
            float s = 0.f;
#pragma unroll
            for (int j = 0; j < 8; j++) {
                float p = ci - nnv[j] + 2.0f * acc[i][j];
                s += fmaxf(p, 0.f);
            }
            sum += mf * s;
        }
    } else {
#pragma unroll
        for (int i = 0; i < 8; i++) {
            int m = m0 + ty * 8 + i;
#pragma unroll
            for (int j = 0; j < 8; j++) {
                int n = n0 + tx * 8 + j;
                float gv = acc[i][j] - (m == n ? 1.0f : 0.0f);
                sum += gv * gv;
            }
        }
    }

    // block reduce
#pragma unroll
    for (int o = 16; o; o >>= 1) sum += __shfl_xor_sync(0xFFFFFFFFu, sum, o);
    __syncthreads();
    float* red = &As[0][0];
    if ((tid & 31) == 0) red[tid >> 5] = sum;
    __syncthreads();
    if (tid == 0) {
        float tot = 0.f;
#pragma unroll
        for (int w = 0; w < 8; w++) tot += red[w];
        atomicAdd(&g_acc[MODE == 0 ? 0 : 2], (double)tot);
    }
}

// focal triplet term: warp per row
__global__ void jt_kernel(const float* __restrict__ g,
                          const float* __restrict__ F,
                          const float* __restrict__ vhat) {
    int row = blockIdx.x * 8 + (threadIdx.x >> 5);
    int lane = threadIdx.x & 31;

    float gl[16];
#pragma unroll
    for (int i = 0; i < 16; i++) gl[i] = g[(size_t)row * KK + i * 32 + lane];

    float vh[8];
#pragma unroll
    for (int i = 0; i < 8; i++) vh[i] = vhat[(size_t)row * DD + lane * 8 + i];

    float cv[TT];
    int ci[TT];
#pragma unroll
    for (int t = 0; t < TT; t++) {
        // local min over 16 (lowest local index wins ties -> lowest global idx per lane)
        float mv = gl[0];
        int mi = 0;
#pragma unroll
        for (int i = 1; i < 16; i++) {
            if (gl[i] < mv) { mv = gl[i]; mi = i; }
        }
        float bv = mv;
        int bidx = mi * 32 + lane;
#pragma unroll
        for (int o = 16; o; o >>= 1) {
            float ov = __shfl_xor_sync(0xFFFFFFFFu, bv, o);
            int oi = __shfl_xor_sync(0xFFFFFFFFu, bidx, o);
            if (ov < bv || (ov == bv && oi < bidx)) { bv = ov; bidx = oi; }
        }
        cv[t] = bv;
        ci[t] = bidx;
        if ((bidx & 31) == lane) gl[bidx >> 5] = 3.4e38f;  // exclude
    }

    float gsum = 0.f;
#pragma unroll
    for (int t = 0; t < TT; t++) gsum += cv[t];
    float denom = gsum + EPSV;
    float td = g_td[row];

    float jt = 0.f;
#pragma unroll
    for (int t = 0; t < TT; t++) {
        const float* Fr = F + (size_t)ci[t] * DD + lane * 8;
        float a = 0.f;
        float4 f0 = *(const float4*)(Fr);
        float4 f1 = *(const float4*)(Fr + 4);
        float d0 = vh[0] - f0.x; a += d0 * d0;
        float d1 = vh[1] - f0.y; a += d1 * d1;
        float d2 = vh[2] - f0.z; a += d2 * d2;
        float d3 = vh[3] - f0.w; a += d3 * d3;
        float d4 = vh[4] - f1.x; a += d4 * d4;
        float d5 = vh[5] - f1.y; a += d5 * d5;
        float d6 = vh[6] - f1.z; a += d6 * d6;
        float d7 = vh[7] - f1.w; a += d7 * d7;
#pragma unroll
        for (int o = 16; o; o >>= 1) a += __shfl_xor_sync(0xFFFFFFFFu, a, o);
        float gt = cv[t] / denom;
        float om = 1.0f - gt;
        float mt = om * om;                 // M_MARGIN = 1.0
        jt += fmaxf(mt + td - a, 0.f);
    }
    if (lane == 0) atomicAdd(&g_acc[1], (double)(jt * g_maskf[row]));
}

__global__ void finalize_kernel(const unsigned char* __restrict__ mask,
                                float* __restrict__ out) {
    __shared__ float sm[256];
    float s = 0.f;
    for (int i = threadIdx.x; i < BB; i += 256) s += mask[i] ? 1.0f : 0.0f;
    sm[threadIdx.x] = s;
    __syncthreads();
    for (int o = 128; o; o >>= 1) {
        if (threadIdx.x < o) sm[threadIdx.x] += sm[threadIdx.x + o];
        __syncthreads();
    }
    if (threadIdx.x == 0) {
        double msum = (double)sm[0];
        double ju = (msum == 0.0) ? 0.0 : g_acc[0] / ((double)NN * msum);
        double jt = (msum == 0.0) ? 0.0 : g_acc[1] / msum;
        double jz = ju + jt + 1e-3 * g_acc[2];   // lambda * ortho^2 == lambda * sum(gram^2)
        out[0] = (float)jz;
    }
}

extern "C" void kernel_launch(void* const* d_in, const int* in_sizes, int n_in,
                              void* d_out, int out_size) {
    const float* v = (const float*)d_in[0];
    const float* vhat = (const float*)d_in[1];
    const float* g = (const float*)d_in[2];
    const float* F = (const float*)d_in[3];
    const float* negs = (const float*)d_in[4];
    const unsigned char* mask = (const unsigned char*)d_in[5];
    float* out = (float*)d_out;

    zero_acc_kernel<<<1, 32>>>();
    prep_b_kernel<<<BB / 8, 256>>>(v, vhat, mask);
    prep_n_kernel<<<NN / 8, 256>>>(negs);

    // Ju: A = vhat [8192 x 256], B = negatives [2048 x 256]
    dim3 gJu(NN / 128, BB / 128);
    gemm_reduce_kernel<0><<<gJu, 256>>>(vhat, negs, DD);

    // ortho: F @ F^T, 512x512
    dim3 gOr(KK / 128, KK / 128);
    gemm_reduce_kernel<1><<<gOr, 256>>>(F, F, DD);

    jt_kernel<<<BB / 8, 256>>>(g, F, vhat);

    finalize_kernel<<<1, 256>>>(mask, out);
}